// round 15
// baseline (speedup 1.0000x reference)
#include <cuda_runtime.h>
#include <cuda_bf16.h>
#include <cuda_fp16.h>
#include <cstdint>

// ---------------------------------------------------------------------------
// BEVSampling (sm_100 baseline PTX):
//  k_prep:      w2 fp32 -> fp16, transposed to [n][k] in gmem
//  k_transpose: NCHW fp32 -> NHWC fp16 features
//  k_mlp_mma:   pos-MLP as single-product fp16 mma.sync GEMM (ldmatrix frags,
//               2 CTAs/SM) -> writes pos into d_out
//  k_sample:    project + packed-tap bilinear sample; rank-balanced chain
//               assignment (warp w gets qi ranks {w, w+8, w+16, w+24}).
// ---------------------------------------------------------------------------

#define NUM_CAMS 6
#define EMBED    128
#define NP       8
#define GQ       10000
#define NPTS     80000
#define FEAT_TOTAL 2872320  // 6*128*(2816+704+176+44)

__device__ __half g_feat[FEAT_TOTAL];   // ~5.7 MB NHWC fp16 scratch
__device__ __half g_w2[256 * 128];      // w2^T fp16, [n][k]

// ---------------------------------------------------------------------------
__global__ __launch_bounds__(256) void k_prep(const float* __restrict__ w2)
{
    int i = blockIdx.x * 256 + threadIdx.x;   // 32768 elements
    if (i >= 32768) return;
    int n = i >> 8, k = i & 255;
    g_w2[n * 256 + k] = __float2half(w2[k * 128 + n]);
}

// ---------------------------------------------------------------------------
__global__ __launch_bounds__(256) void k_transpose(
    const float* __restrict__ f0, const float* __restrict__ f1,
    const float* __restrict__ f2, const float* __restrict__ f3)
{
    __shared__ float s[32 * 33];
    int bid = blockIdx.x;
    const float* src; int HW, ptiles, loff, tl;
    if (bid < 2112)      { src = f0; HW = 2816; ptiles = 88; loff = 0;       tl = bid; }
    else if (bid < 2640) { src = f1; HW = 704;  ptiles = 22; loff = 2162688; tl = bid - 2112; }
    else if (bid < 2784) { src = f2; HW = 176;  ptiles = 6;  loff = 2703360; tl = bid - 2640; }
    else                 { src = f3; HW = 44;   ptiles = 2;  loff = 2838528; tl = bid - 2784; }

    int per_cam = ptiles * 4;
    int cam = tl / per_cam;
    int r   = tl - cam * per_cam;
    int c0  = (r & 3) * 32;
    int p0  = (r >> 2) * 32;
    int tx = threadIdx.x, ty = threadIdx.y;

    const float* sp = src + (long)cam * 128 * HW;
    #pragma unroll
    for (int j = 0; j < 4; ++j) {
        int cl = ty + j * 8;
        int p  = p0 + tx;
        float v = (p < HW) ? sp[(c0 + cl) * HW + p] : 0.f;
        s[tx * 33 + cl] = v;
    }
    __syncthreads();
    __half* dst = g_feat + loff + (long)cam * HW * 128;
    #pragma unroll
    for (int j = 0; j < 4; ++j) {
        int pl = ty + j * 8;
        int p  = p0 + pl;
        if (p < HW) dst[p * 128 + c0 + tx] = __float2half(s[pl * 33 + tx]);
    }
}

// ---------------------------------------------------------------------------
__device__ __forceinline__ uint32_t smem_u32(const void* p) {
    return (uint32_t)__cvta_generic_to_shared(p);
}
__device__ __forceinline__ void ldsm_x4(uint32_t* r, uint32_t addr) {
    asm volatile(
        "ldmatrix.sync.aligned.m8n8.x4.shared.b16 {%0,%1,%2,%3}, [%4];"
        : "=r"(r[0]), "=r"(r[1]), "=r"(r[2]), "=r"(r[3]) : "r"(addr));
}
__device__ __forceinline__ void mma_f16(float* d,
    uint32_t a0, uint32_t a1, uint32_t a2, uint32_t a3,
    uint32_t b0, uint32_t b1)
{
    asm volatile(
        "mma.sync.aligned.m16n8k16.row.col.f32.f16.f16.f32 "
        "{%0,%1,%2,%3}, {%4,%5,%6,%7}, {%8,%9}, {%0,%1,%2,%3};"
        : "+f"(d[0]), "+f"(d[1]), "+f"(d[2]), "+f"(d[3])
        : "r"(a0), "r"(a1), "r"(a2), "r"(a3), "r"(b0), "r"(b1));
}

// ---------------------------------------------------------------------------
// K1 (unchanged from R12): fp16 single-product mma, ldmatrix, 2 CTAs/SM.
// ---------------------------------------------------------------------------
#define K1_TILES 625
#define K1_GRID  296
#define SA 136
#define SB 264
#define SM_B2   0
#define SM_B1   512
#define SM_W1   1536
#define SM_REF  4608
#define SM_A    6144
#define SM_Bm   40960
#define K1_SMEM 108544

__global__ __launch_bounds__(256, 2) void k_mlp_mma(
    const float* __restrict__ ref,
    const float* __restrict__ w1,
    const float* __restrict__ b1,
    const float* __restrict__ b2,
    float* __restrict__ out)
{
    extern __shared__ char smb[];
    float* b2s  = (float*)(smb + SM_B2);
    float* b1s  = (float*)(smb + SM_B1);
    float* w1s  = (float*)(smb + SM_W1);
    float* refs = (float*)(smb + SM_REF);
    __half* Ah  = (__half*)(smb + SM_A);
    __half* Bh  = (__half*)(smb + SM_Bm);
    float* S    = (float*)(smb + SM_A);   // epilogue alias [c][66]

    const int t    = threadIdx.x;
    const int wid  = t >> 5;
    const int lane = t & 31;
    const int mw   = wid >> 1;
    const int nw   = (wid & 1) * 64;

    const uint32_t aBase = smem_u32(smb + SM_A);
    const uint32_t bBase = smem_u32(smb + SM_Bm);

    for (int i = t; i < 768; i += 256) w1s[i] = w1[i];
    if (t < 256) b1s[t] = b1[t];
    if (t < 128) b2s[t] = b2[t];
    for (int i = t; i < 128 * 32; i += 256) {
        int n = i >> 5, j = i & 31;
        *(uint4*)(Bh + n * SB + j * 8) = ((const uint4*)(g_w2 + n * 256))[j];
    }

    const int aRow = lane & 15;
    const int aK8  = (lane >> 4) << 3;
    const int bRow = (lane & 7) + ((lane >> 4) << 3);
    const int bK8  = ((lane >> 3) & 1) << 3;

    for (int tile = blockIdx.x; tile < K1_TILES; tile += K1_GRID) {
        const int n0 = tile * 128;

        __syncthreads();
        for (int i = t; i < 384; i += 256) {
            int d = i >> 7, r = i & 127;
            refs[d * 128 + r] = ref[(n0 + r) * 3 + d];
        }

        float acc[2][8][4];
        #pragma unroll
        for (int mt = 0; mt < 2; ++mt)
            #pragma unroll
            for (int nt = 0; nt < 8; ++nt)
                #pragma unroll
                for (int j = 0; j < 4; ++j) acc[mt][nt][j] = 0.f;

        for (int chunk = 0; chunk < 2; ++chunk) {
            const int kb = chunk * 128;
            __syncthreads();

            for (int i = t; i < 128 * 64; i += 256) {
                int row = i >> 6, kp = i & 63;
                int k = kb + kp * 2;
                float x = refs[row], y = refs[128 + row], z = refs[256 + row];
                float h0 = fmaxf(fmaf(x, w1s[k],
                                 fmaf(y, w1s[256 + k],
                                 fmaf(z, w1s[512 + k], b1s[k]))), 0.f);
                float h1 = fmaxf(fmaf(x, w1s[k + 1],
                                 fmaf(y, w1s[256 + k + 1],
                                 fmaf(z, w1s[512 + k + 1], b1s[k + 1]))), 0.f);
                *(__half2*)(Ah + row * SA + kp * 2) = __floats2half2_rn(h0, h1);
            }
            __syncthreads();

            #pragma unroll
            for (int ks = 0; ks < 8; ++ks) {
                const int k0 = ks * 16;
                const int kg = kb + k0;
                uint32_t a[2][4];
                #pragma unroll
                for (int mt = 0; mt < 2; ++mt) {
                    uint32_t addr = aBase +
                        (((mw * 32 + mt * 16 + aRow) * SA) + k0 + aK8) * 2;
                    ldsm_x4(a[mt], addr);
                }
                uint32_t b[8][2];
                #pragma unroll
                for (int ntp = 0; ntp < 4; ++ntp) {
                    uint32_t addr = bBase +
                        (((nw + ntp * 16 + bRow) * SB) + kg + bK8) * 2;
                    uint32_t r[4];
                    ldsm_x4(r, addr);
                    b[ntp * 2][0]     = r[0];
                    b[ntp * 2][1]     = r[1];
                    b[ntp * 2 + 1][0] = r[2];
                    b[ntp * 2 + 1][1] = r[3];
                }
                #pragma unroll
                for (int nt = 0; nt < 8; ++nt)
                    #pragma unroll
                    for (int mt = 0; mt < 2; ++mt)
                        mma_f16(acc[mt][nt], a[mt][0], a[mt][1], a[mt][2],
                                a[mt][3], b[nt][0], b[nt][1]);
            }
        }
        __syncthreads();

        if (mw < 2) {
            #pragma unroll
            for (int mt = 0; mt < 2; ++mt)
                #pragma unroll
                for (int nt = 0; nt < 8; ++nt) {
                    int r = mw * 32 + mt * 16 + (lane >> 2);
                    int c = nw + nt * 8 + (lane & 3) * 2;
                    S[c * 66 + r]           = acc[mt][nt][0];
                    S[(c + 1) * 66 + r]     = acc[mt][nt][1];
                    S[c * 66 + r + 8]       = acc[mt][nt][2];
                    S[(c + 1) * 66 + r + 8] = acc[mt][nt][3];
                }
        }
        __syncthreads();
        for (int i = t; i < 128 * 64; i += 256) {
            int c = i >> 6, m = i & 63;
            out[c * NPTS + n0 + m] = S[c * 66 + m] + b2s[c];
        }
        __syncthreads();

        if (mw >= 2) {
            #pragma unroll
            for (int mt = 0; mt < 2; ++mt)
                #pragma unroll
                for (int nt = 0; nt < 8; ++nt) {
                    int r = (mw - 2) * 32 + mt * 16 + (lane >> 2);
                    int c = nw + nt * 8 + (lane & 3) * 2;
                    S[c * 66 + r]           = acc[mt][nt][0];
                    S[(c + 1) * 66 + r]     = acc[mt][nt][1];
                    S[c * 66 + r + 8]       = acc[mt][nt][2];
                    S[(c + 1) * 66 + r + 8] = acc[mt][nt][3];
                }
        }
        __syncthreads();
        for (int i = t; i < 128 * 64; i += 256) {
            int c = i >> 6, m = i & 63;
            out[c * NPTS + n0 + 64 + m] = S[c * 66 + m] + b2s[c];
        }
    }
}

// ---------------------------------------------------------------------------
// K2: R12 config (6 CTAs/SM, float4 weights, 4 chains/warp) + rank-balanced
// chain assignment: warp w processes qi of count-ranks {w, w+8, w+16, w+24},
// so the heaviest 8 queries land one per warp -> per-warp nmax ~ balanced.
// ---------------------------------------------------------------------------
__global__ __launch_bounds__(256, 6) void k_sample(
    const float* __restrict__ ref,   // [8, 10000, 3] normalized
    const float* __restrict__ l2i,   // [6,4,4]
    float* __restrict__ out)         // [128, 8, 10000]
{
    __shared__ float  refc[96];
    __shared__ float  l2is[96];
    __shared__ float  um[NUM_CAMS * 32];
    __shared__ float  vm[NUM_CAMS * 32];
    __shared__ int    vld[NUM_CAMS * 32];
    __shared__ int    cnt[32];
    __shared__ int    perm[32];          // perm[rank] = qi
    __shared__ int    entO[32 * 24];
    __shared__ float4 entW[32 * 24];
    __shared__ float  S[EMBED * 33];

    const int t  = threadIdx.x;
    const int p  = blockIdx.y;
    const int q0 = blockIdx.x * 32;

    if (t < 96) {
        l2is[t] = l2i[t];
        int qi = t & 31, d = t >> 5;
        int q = q0 + qi;
        refc[(d << 5) + qi] = (q < GQ) ? ref[(p * GQ + q) * 3 + d] : 0.f;
    }
    __syncthreads();

    if (t < 192) {
        int qi = t & 31, cam = t >> 5;
        float rx = refc[qi], ry = refc[32 + qi], rz = refc[64 + qi];
        float px = fmaf(rx, 100.f, -50.f);
        float py = fmaf(ry, 100.f, -50.f);
        float pz = fmaf(rz,   8.f,  -4.f);
        const float* M = &l2is[cam * 16];
        float cx = fmaf(M[0], px, fmaf(M[1],  py, fmaf(M[2],  pz, M[3])));
        float cy = fmaf(M[4], px, fmaf(M[5],  py, fmaf(M[6],  pz, M[7])));
        float cz = fmaf(M[8], px, fmaf(M[9],  py, fmaf(M[10], pz, M[11])));
        float zs = fmaxf(cz, 1e-6f);
        float u = __fdiv_rn(__fdiv_rn(cx, zs), 704.f);
        float v = __fdiv_rn(__fdiv_rn(cy, zs), 256.f);
        um[cam * 32 + qi] = u;
        vm[cam * 32 + qi] = v;
        vld[cam * 32 + qi] = (cz > 1e-6f) & (u > 0.f) & (u < 1.f)
                           & (v > 0.f) & (v < 1.f);
    }
    __syncthreads();

    if (t < 192) {
        int qi = t & 31, cam = t >> 5;
        if (vld[cam * 32 + qi]) {
            int rank = 0;
            for (int pc = 0; pc < cam; ++pc) rank += vld[pc * 32 + qi];
            float u = um[cam * 32 + qi];
            float v = vm[cam * 32 + qi];
            const int LW_[4]   = {88, 44, 22, 11};
            const int LH_[4]   = {32, 16, 8, 4};
            const int LHW_[4]  = {2816, 704, 176, 44};
            const int LOFF_[4] = {0, 2162688, 2703360, 2838528};
            #pragma unroll
            for (int l = 0; l < 4; ++l) {
                const int W = LW_[l], H = LH_[l];
                float x = fmaf(u, (float)W, -0.5f);
                float y = fmaf(v, (float)H, -0.5f);
                float xf = floorf(x), yf = floorf(y);
                float wx = x - xf,   wy = y - yf;
                int x0 = (int)xf, y0 = (int)yf;
                int xc0 = min(max(x0, 0), W - 1);
                int xc1 = min(max(x0 + 1, 0), W - 1);
                int yc0 = min(max(y0, 0), H - 1);
                int yc1 = min(max(y0 + 1, 0), H - 1);
                float okx0 = (x0 >= 0  && x0 < W)     ? 1.f : 0.f;
                float okx1 = (x0 >= -1 && x0 < W - 1) ? 1.f : 0.f;
                float oky0 = (y0 >= 0  && y0 < H)     ? 1.f : 0.f;
                float oky1 = (y0 >= -1 && y0 < H - 1) ? 1.f : 0.f;
                int base = LOFF_[l] + cam * (LHW_[l] << 7)
                         + ((yc0 * W + xc0) << 7);
                int code = base | (xc1 > xc0 ? 1 : 0)
                                | (yc1 > yc0 ? 2 : 0) | (l << 2);
                float4 Wt;
                Wt.x = (1.f - wx) * (1.f - wy) * okx0 * oky0 * 0.25f;
                Wt.y = wx         * (1.f - wy) * okx1 * oky0 * 0.25f;
                Wt.z = (1.f - wx) * wy         * okx0 * oky1 * 0.25f;
                Wt.w = wx         * wy         * okx1 * oky1 * 0.25f;
                int slot = qi * 24 + rank * 4 + l;
                entO[slot] = code;
                entW[slot] = Wt;
            }
        }
    }
    if (t < 32) {
        int s = 0;
        #pragma unroll
        for (int pc = 0; pc < NUM_CAMS; ++pc) s += vld[pc * 32 + t];
        cnt[t] = s * 4;
    }
    __syncthreads();

    // deterministic count-rank (index tiebreak); perm[rank] = qi
    if (t < 32) {
        int my = cnt[t];
        int rank = 0;
        #pragma unroll
        for (int j = 0; j < 32; ++j) {
            int cj = cnt[j];
            rank += (cj < my) || (cj == my && j < t);
        }
        perm[rank] = t;
    }
    __syncthreads();

    // phase 3: 4 rank-balanced qi chains per warp
    const int wid  = t >> 5;
    const int lane = t & 31;
    const int c0   = lane * 4;

    {
        int qsel[4];
        int n[4];
        float4 acc[4];
        int nmax = 0;
        #pragma unroll
        for (int j = 0; j < 4; ++j) {
            qsel[j] = perm[wid + j * 8];
            n[j]    = cnt[qsel[j]];
            acc[j]  = make_float4(0.f, 0.f, 0.f, 0.f);
            nmax    = max(nmax, n[j]);
        }
        for (int e = 0; e < nmax; ++e) {
            #pragma unroll
            for (int j = 0; j < 4; ++j) {
                if (e < n[j]) {
                    int qi = qsel[j];
                    int    pk = entO[qi * 24 + e];
                    float4 Wt = entW[qi * 24 + e];
                    int lvl  = (pk >> 2) & 3;
                    int dx   = (pk & 1) << 7;
                    int dy   = (pk & 2) ? (11264 >> lvl) : 0;
                    const __half* fb = g_feat + (pk & ~127) + c0;
                    uint2 r0 = *(const uint2*)(fb);
                    uint2 r1 = *(const uint2*)(fb + dx);
                    uint2 r2 = *(const uint2*)(fb + dy);
                    uint2 r3 = *(const uint2*)(fb + dy + dx);
                    float2 a0 = __half22float2(*(__half2*)&r0.x);
                    float2 a1 = __half22float2(*(__half2*)&r0.y);
                    float2 b0 = __half22float2(*(__half2*)&r1.x);
                    float2 b1 = __half22float2(*(__half2*)&r1.y);
                    float2 c2 = __half22float2(*(__half2*)&r2.x);
                    float2 c3 = __half22float2(*(__half2*)&r2.y);
                    float2 d0 = __half22float2(*(__half2*)&r3.x);
                    float2 d1 = __half22float2(*(__half2*)&r3.y);
                    acc[j].x = fmaf(Wt.x, a0.x, fmaf(Wt.y, b0.x,
                               fmaf(Wt.z, c2.x, fmaf(Wt.w, d0.x, acc[j].x))));
                    acc[j].y = fmaf(Wt.x, a0.y, fmaf(Wt.y, b0.y,
                               fmaf(Wt.z, c2.y, fmaf(Wt.w, d0.y, acc[j].y))));
                    acc[j].z = fmaf(Wt.x, a1.x, fmaf(Wt.y, b1.x,
                               fmaf(Wt.z, c3.x, fmaf(Wt.w, d1.x, acc[j].z))));
                    acc[j].w = fmaf(Wt.x, a1.y, fmaf(Wt.y, b1.y,
                               fmaf(Wt.z, c3.y, fmaf(Wt.w, d1.y, acc[j].w))));
                }
            }
        }
        #pragma unroll
        for (int j = 0; j < 4; ++j) {
            int qi = qsel[j];
            S[(c0 + 0) * 33 + qi] = acc[j].x;
            S[(c0 + 1) * 33 + qi] = acc[j].y;
            S[(c0 + 2) * 33 + qi] = acc[j].z;
            S[(c0 + 3) * 33 + qi] = acc[j].w;
        }
    }
    __syncthreads();

    // coalesced RMW: out += sampled (pos written by k_mlp_mma)
    for (int e = t; e < EMBED * 32; e += 256) {
        int cc = e >> 5, qi = e & 31;
        int q = q0 + qi;
        if (q < GQ) {
            int oi = (cc * NP + p) * GQ + q;
            out[oi] += S[cc * 33 + qi];
        }
    }
}

// ---------------------------------------------------------------------------
extern "C" void kernel_launch(void* const* d_in, const int* in_sizes, int n_in,
                              void* d_out, int out_size)
{
    const float* f0  = (const float*)d_in[0];
    const float* f1  = (const float*)d_in[1];
    const float* f2  = (const float*)d_in[2];
    const float* f3  = (const float*)d_in[3];
    const float* ref = (const float*)d_in[4];
    const float* l2i = (const float*)d_in[5];
    const float* w1  = (const float*)d_in[6];
    const float* b1  = (const float*)d_in[7];
    const float* w2  = (const float*)d_in[8];
    const float* b2  = (const float*)d_in[9];
    float* out = (float*)d_out;

    k_prep<<<128, 256>>>(w2);
    k_transpose<<<2832, dim3(32, 8)>>>(f0, f1, f2, f3);

    cudaFuncSetAttribute(k_mlp_mma, cudaFuncAttributeMaxDynamicSharedMemorySize,
                         K1_SMEM);
    k_mlp_mma<<<K1_GRID, 256, K1_SMEM>>>(ref, w1, b1, b2, out);

    dim3 grid((GQ + 31) / 32, NP);
    k_sample<<<grid, 256>>>(ref, l2i, out);
}

// round 16
// speedup vs baseline: 1.0814x; 1.0814x over previous
#include <cuda_runtime.h>
#include <cuda_bf16.h>
#include <cuda_fp16.h>
#include <cstdint>

// ---------------------------------------------------------------------------
// BEVSampling (sm_100 baseline PTX):
//  k_transpose: NCHW fp32 -> NHWC fp16 features; 128 extra blocks fold in the
//               w2 fp32 -> fp16 transpose prep (one fewer launch)
//  k_mlp_mma:   pos-MLP as single-product fp16 mma.sync GEMM; 2 full tiles
//               per CTA + 66 half-tiles for tail balance (2.5T vs 3T)
//  k_sample:    exact R12 config (best measured): 6 CTAs/SM, float4 weights,
//               4 interleaved chains/warp, packed 4B tap codes
// ---------------------------------------------------------------------------

#define NUM_CAMS 6
#define EMBED    128
#define NP       8
#define GQ       10000
#define NPTS     80000
#define FEAT_TOTAL 2872320  // 6*128*(2816+704+176+44)

__device__ __half g_feat[FEAT_TOTAL];   // ~5.7 MB NHWC fp16 scratch
__device__ __half g_w2[256 * 128];      // w2^T fp16, [n][k]

// ---------------------------------------------------------------------------
// k_transpose (+ folded w2 prep in blocks >= 2832)
// ---------------------------------------------------------------------------
__global__ __launch_bounds__(256) void k_transpose(
    const float* __restrict__ f0, const float* __restrict__ f1,
    const float* __restrict__ f2, const float* __restrict__ f3,
    const float* __restrict__ w2)
{
    __shared__ float s[32 * 33];
    int bid = blockIdx.x;
    int tx = threadIdx.x, ty = threadIdx.y;

    if (bid >= 2832) {                       // folded k_prep
        int i = (bid - 2832) * 256 + ty * 32 + tx;   // 32768 elements
        int n = i >> 8, k = i & 255;
        g_w2[n * 256 + k] = __float2half(w2[k * 128 + n]);
        return;
    }

    const float* src; int HW, ptiles, loff, tl;
    if (bid < 2112)      { src = f0; HW = 2816; ptiles = 88; loff = 0;       tl = bid; }
    else if (bid < 2640) { src = f1; HW = 704;  ptiles = 22; loff = 2162688; tl = bid - 2112; }
    else if (bid < 2784) { src = f2; HW = 176;  ptiles = 6;  loff = 2703360; tl = bid - 2640; }
    else                 { src = f3; HW = 44;   ptiles = 2;  loff = 2838528; tl = bid - 2784; }

    int per_cam = ptiles * 4;
    int cam = tl / per_cam;
    int r   = tl - cam * per_cam;
    int c0  = (r & 3) * 32;
    int p0  = (r >> 2) * 32;

    const float* sp = src + (long)cam * 128 * HW;
    #pragma unroll
    for (int j = 0; j < 4; ++j) {
        int cl = ty + j * 8;
        int p  = p0 + tx;
        float v = (p < HW) ? sp[(c0 + cl) * HW + p] : 0.f;
        s[tx * 33 + cl] = v;
    }
    __syncthreads();
    __half* dst = g_feat + loff + (long)cam * HW * 128;
    #pragma unroll
    for (int j = 0; j < 4; ++j) {
        int pl = ty + j * 8;
        int p  = p0 + pl;
        if (p < HW) dst[p * 128 + c0 + tx] = __float2half(s[pl * 33 + tx]);
    }
}

// ---------------------------------------------------------------------------
__device__ __forceinline__ uint32_t smem_u32(const void* p) {
    return (uint32_t)__cvta_generic_to_shared(p);
}
__device__ __forceinline__ void ldsm_x4(uint32_t* r, uint32_t addr) {
    asm volatile(
        "ldmatrix.sync.aligned.m8n8.x4.shared.b16 {%0,%1,%2,%3}, [%4];"
        : "=r"(r[0]), "=r"(r[1]), "=r"(r[2]), "=r"(r[3]) : "r"(addr));
}
__device__ __forceinline__ void mma_f16(float* d,
    uint32_t a0, uint32_t a1, uint32_t a2, uint32_t a3,
    uint32_t b0, uint32_t b1)
{
    asm volatile(
        "mma.sync.aligned.m16n8k16.row.col.f32.f16.f16.f32 "
        "{%0,%1,%2,%3}, {%4,%5,%6,%7}, {%8,%9}, {%0,%1,%2,%3};"
        : "+f"(d[0]), "+f"(d[1]), "+f"(d[2]), "+f"(d[3])
        : "r"(a0), "r"(a1), "r"(a2), "r"(a3), "r"(b0), "r"(b1));
}

// ---------------------------------------------------------------------------
// K1: out[c*80000+n] = (relu(ref@w1+b1) @ w2)[n][c] + b2[c]
// Work units per CTA b: full tiles b and b+296 (rows=128); CTAs 0-65 also do
// half-tile (rows=64) covering the last 33 tiles. Critical path 2.5 tiles.
// ---------------------------------------------------------------------------
#define K1_GRID  296
#define SA 136
#define SB 264
#define SM_B2   0
#define SM_B1   512
#define SM_W1   1536
#define SM_REF  4608
#define SM_A    6144
#define SM_Bm   40960
#define K1_SMEM 108544

__global__ __launch_bounds__(256, 2) void k_mlp_mma(
    const float* __restrict__ ref,
    const float* __restrict__ w1,
    const float* __restrict__ b1,
    const float* __restrict__ b2,
    float* __restrict__ out)
{
    extern __shared__ char smb[];
    float* b2s  = (float*)(smb + SM_B2);
    float* b1s  = (float*)(smb + SM_B1);
    float* w1s  = (float*)(smb + SM_W1);
    float* refs = (float*)(smb + SM_REF);
    __half* Ah  = (__half*)(smb + SM_A);
    __half* Bh  = (__half*)(smb + SM_Bm);
    float* S    = (float*)(smb + SM_A);   // epilogue alias [c][66]

    const int t    = threadIdx.x;
    const int wid  = t >> 5;
    const int lane = t & 31;
    const int mw   = wid >> 1;
    const int nw   = (wid & 1) * 64;

    const uint32_t aBase = smem_u32(smb + SM_A);
    const uint32_t bBase = smem_u32(smb + SM_Bm);

    for (int i = t; i < 768; i += 256) w1s[i] = w1[i];
    if (t < 256) b1s[t] = b1[t];
    if (t < 128) b2s[t] = b2[t];
    for (int i = t; i < 128 * 32; i += 256) {
        int n = i >> 5, j = i & 31;
        *(uint4*)(Bh + n * SB + j * 8) = ((const uint4*)(g_w2 + n * 256))[j];
    }

    const int aRow = lane & 15;
    const int aK8  = (lane >> 4) << 3;
    const int bRow = (lane & 7) + ((lane >> 4) << 3);
    const int bK8  = ((lane >> 3) & 1) << 3;

    const int b = blockIdx.x;
    const int nunits = (b < 66) ? 3 : 2;

    for (int unit = 0; unit < nunits; ++unit) {
        int n0, rows;
        if (unit == 0)      { n0 = b * 128;            rows = 128; }
        else if (unit == 1) { n0 = (b + K1_GRID) * 128; rows = 128; }
        else                { n0 = 75776 + b * 64;      rows = 64;  }

        __syncthreads();   // prior unit's S reads done; B staged (first unit)
        for (int i = t; i < 3 * rows; i += 256) {
            int d = i / rows, r = i - d * rows;
            refs[d * 128 + r] = ref[(n0 + r) * 3 + d];
        }

        float acc[2][8][4];
        #pragma unroll
        for (int mt = 0; mt < 2; ++mt)
            #pragma unroll
            for (int nt = 0; nt < 8; ++nt)
                #pragma unroll
                for (int j = 0; j < 4; ++j) acc[mt][nt][j] = 0.f;

        for (int chunk = 0; chunk < 2; ++chunk) {
            const int kb = chunk * 128;
            __syncthreads();   // refs ready / prior chunk frag reads done

            for (int i = t; i < rows * 64; i += 256) {
                int row = i >> 6, kp = i & 63;
                int k = kb + kp * 2;
                float x = refs[row], y = refs[128 + row], z = refs[256 + row];
                float h0 = fmaxf(fmaf(x, w1s[k],
                                 fmaf(y, w1s[256 + k],
                                 fmaf(z, w1s[512 + k], b1s[k]))), 0.f);
                float h1 = fmaxf(fmaf(x, w1s[k + 1],
                                 fmaf(y, w1s[256 + k + 1],
                                 fmaf(z, w1s[512 + k + 1], b1s[k + 1]))), 0.f);
                *(__half2*)(Ah + row * SA + kp * 2) = __floats2half2_rn(h0, h1);
            }
            __syncthreads();

            if (mw * 32 < rows) {
                #pragma unroll
                for (int ks = 0; ks < 8; ++ks) {
                    const int k0 = ks * 16;
                    const int kg = kb + k0;
                    uint32_t a[2][4];
                    #pragma unroll
                    for (int mt = 0; mt < 2; ++mt) {
                        uint32_t addr = aBase +
                            (((mw * 32 + mt * 16 + aRow) * SA) + k0 + aK8) * 2;
                        ldsm_x4(a[mt], addr);
                    }
                    uint32_t bfr[8][2];
                    #pragma unroll
                    for (int ntp = 0; ntp < 4; ++ntp) {
                        uint32_t addr = bBase +
                            (((nw + ntp * 16 + bRow) * SB) + kg + bK8) * 2;
                        uint32_t r[4];
                        ldsm_x4(r, addr);
                        bfr[ntp * 2][0]     = r[0];
                        bfr[ntp * 2][1]     = r[1];
                        bfr[ntp * 2 + 1][0] = r[2];
                        bfr[ntp * 2 + 1][1] = r[3];
                    }
                    #pragma unroll
                    for (int nt = 0; nt < 8; ++nt)
                        #pragma unroll
                        for (int mt = 0; mt < 2; ++mt)
                            mma_f16(acc[mt][nt], a[mt][0], a[mt][1], a[mt][2],
                                    a[mt][3], bfr[nt][0], bfr[nt][1]);
                }
            }
        }
        __syncthreads();   // frag reads done before S aliases A

        // epilogue pass 0: rows 0-63 (warps mw 0,1)
        if (mw < 2) {
            #pragma unroll
            for (int mt = 0; mt < 2; ++mt)
                #pragma unroll
                for (int nt = 0; nt < 8; ++nt) {
                    int r = mw * 32 + mt * 16 + (lane >> 2);
                    int c = nw + nt * 8 + (lane & 3) * 2;
                    S[c * 66 + r]           = acc[mt][nt][0];
                    S[(c + 1) * 66 + r]     = acc[mt][nt][1];
                    S[c * 66 + r + 8]       = acc[mt][nt][2];
                    S[(c + 1) * 66 + r + 8] = acc[mt][nt][3];
                }
        }
        __syncthreads();
        for (int i = t; i < 128 * 64; i += 256) {
            int c = i >> 6, m = i & 63;
            out[c * NPTS + n0 + m] = S[c * 66 + m] + b2s[c];
        }

        if (rows == 128) {
            __syncthreads();
            // epilogue pass 1: rows 64-127 (warps mw 2,3)
            if (mw >= 2) {
                #pragma unroll
                for (int mt = 0; mt < 2; ++mt)
                    #pragma unroll
                    for (int nt = 0; nt < 8; ++nt) {
                        int r = (mw - 2) * 32 + mt * 16 + (lane >> 2);
                        int c = nw + nt * 8 + (lane & 3) * 2;
                        S[c * 66 + r]           = acc[mt][nt][0];
                        S[(c + 1) * 66 + r]     = acc[mt][nt][1];
                        S[c * 66 + r + 8]       = acc[mt][nt][2];
                        S[(c + 1) * 66 + r + 8] = acc[mt][nt][3];
                    }
            }
            __syncthreads();
            for (int i = t; i < 128 * 64; i += 256) {
                int c = i >> 6, m = i & 63;
                out[c * NPTS + n0 + 64 + m] = S[c * 66 + m] + b2s[c];
            }
        }
    }
}

// ---------------------------------------------------------------------------
// K2 (exact R12 config: 6 CTAs/SM, float4 weights, 4 chains/warp, 40 regs).
// ---------------------------------------------------------------------------
__global__ __launch_bounds__(256, 6) void k_sample(
    const float* __restrict__ ref,   // [8, 10000, 3] normalized
    const float* __restrict__ l2i,   // [6,4,4]
    float* __restrict__ out)         // [128, 8, 10000]
{
    __shared__ float  refc[96];
    __shared__ float  l2is[96];
    __shared__ float  um[NUM_CAMS * 32];
    __shared__ float  vm[NUM_CAMS * 32];
    __shared__ int    vld[NUM_CAMS * 32];
    __shared__ int    cnt[32];
    __shared__ int    entO[32 * 24];
    __shared__ float4 entW[32 * 24];
    __shared__ float  S[EMBED * 33];

    const int t  = threadIdx.x;
    const int p  = blockIdx.y;
    const int q0 = blockIdx.x * 32;

    if (t < 96) {
        l2is[t] = l2i[t];
        int qi = t & 31, d = t >> 5;
        int q = q0 + qi;
        refc[(d << 5) + qi] = (q < GQ) ? ref[(p * GQ + q) * 3 + d] : 0.f;
    }
    __syncthreads();

    if (t < 192) {
        int qi = t & 31, cam = t >> 5;
        float rx = refc[qi], ry = refc[32 + qi], rz = refc[64 + qi];
        float px = fmaf(rx, 100.f, -50.f);
        float py = fmaf(ry, 100.f, -50.f);
        float pz = fmaf(rz,   8.f,  -4.f);
        const float* M = &l2is[cam * 16];
        float cx = fmaf(M[0], px, fmaf(M[1],  py, fmaf(M[2],  pz, M[3])));
        float cy = fmaf(M[4], px, fmaf(M[5],  py, fmaf(M[6],  pz, M[7])));
        float cz = fmaf(M[8], px, fmaf(M[9],  py, fmaf(M[10], pz, M[11])));
        float zs = fmaxf(cz, 1e-6f);
        float u = __fdiv_rn(__fdiv_rn(cx, zs), 704.f);
        float v = __fdiv_rn(__fdiv_rn(cy, zs), 256.f);
        um[cam * 32 + qi] = u;
        vm[cam * 32 + qi] = v;
        vld[cam * 32 + qi] = (cz > 1e-6f) & (u > 0.f) & (u < 1.f)
                           & (v > 0.f) & (v < 1.f);
    }
    __syncthreads();

    if (t < 192) {
        int qi = t & 31, cam = t >> 5;
        if (vld[cam * 32 + qi]) {
            int rank = 0;
            for (int pc = 0; pc < cam; ++pc) rank += vld[pc * 32 + qi];
            float u = um[cam * 32 + qi];
            float v = vm[cam * 32 + qi];
            const int LW_[4]   = {88, 44, 22, 11};
            const int LH_[4]   = {32, 16, 8, 4};
            const int LHW_[4]  = {2816, 704, 176, 44};
            const int LOFF_[4] = {0, 2162688, 2703360, 2838528};
            #pragma unroll
            for (int l = 0; l < 4; ++l) {
                const int W = LW_[l], H = LH_[l];
                float x = fmaf(u, (float)W, -0.5f);
                float y = fmaf(v, (float)H, -0.5f);
                float xf = floorf(x), yf = floorf(y);
                float wx = x - xf,   wy = y - yf;
                int x0 = (int)xf, y0 = (int)yf;
                int xc0 = min(max(x0, 0), W - 1);
                int xc1 = min(max(x0 + 1, 0), W - 1);
                int yc0 = min(max(y0, 0), H - 1);
                int yc1 = min(max(y0 + 1, 0), H - 1);
                float okx0 = (x0 >= 0  && x0 < W)     ? 1.f : 0.f;
                float okx1 = (x0 >= -1 && x0 < W - 1) ? 1.f : 0.f;
                float oky0 = (y0 >= 0  && y0 < H)     ? 1.f : 0.f;
                float oky1 = (y0 >= -1 && y0 < H - 1) ? 1.f : 0.f;
                int base = LOFF_[l] + cam * (LHW_[l] << 7)
                         + ((yc0 * W + xc0) << 7);
                int code = base | (xc1 > xc0 ? 1 : 0)
                                | (yc1 > yc0 ? 2 : 0) | (l << 2);
                float4 Wt;
                Wt.x = (1.f - wx) * (1.f - wy) * okx0 * oky0 * 0.25f;
                Wt.y = wx         * (1.f - wy) * okx1 * oky0 * 0.25f;
                Wt.z = (1.f - wx) * wy         * okx0 * oky1 * 0.25f;
                Wt.w = wx         * wy         * okx1 * oky1 * 0.25f;
                int slot = qi * 24 + rank * 4 + l;
                entO[slot] = code;
                entW[slot] = Wt;
            }
        }
    }
    if (t < 32) {
        int s = 0;
        #pragma unroll
        for (int pc = 0; pc < NUM_CAMS; ++pc) s += vld[pc * 32 + t];
        cnt[t] = s * 4;
    }
    __syncthreads();

    const int wid  = t >> 5;
    const int lane = t & 31;
    const int c0   = lane * 4;

    {
        int n[4];
        float4 acc[4];
        int nmax = 0;
        #pragma unroll
        for (int j = 0; j < 4; ++j) {
            int qi = wid + j * 8;
            n[j]   = cnt[qi];
            acc[j] = make_float4(0.f, 0.f, 0.f, 0.f);
            nmax   = max(nmax, n[j]);
        }
        for (int e = 0; e < nmax; ++e) {
            #pragma unroll
            for (int j = 0; j < 4; ++j) {
                if (e < n[j]) {
                    int qi = wid + j * 8;
                    int    pk = entO[qi * 24 + e];
                    float4 Wt = entW[qi * 24 + e];
                    int lvl  = (pk >> 2) & 3;
                    int dx   = (pk & 1) << 7;
                    int dy   = (pk & 2) ? (11264 >> lvl) : 0;
                    const __half* fb = g_feat + (pk & ~127) + c0;
                    uint2 r0 = *(const uint2*)(fb);
                    uint2 r1 = *(const uint2*)(fb + dx);
                    uint2 r2 = *(const uint2*)(fb + dy);
                    uint2 r3 = *(const uint2*)(fb + dy + dx);
                    float2 a0 = __half22float2(*(__half2*)&r0.x);
                    float2 a1 = __half22float2(*(__half2*)&r0.y);
                    float2 b0 = __half22float2(*(__half2*)&r1.x);
                    float2 b1 = __half22float2(*(__half2*)&r1.y);
                    float2 c2 = __half22float2(*(__half2*)&r2.x);
                    float2 c3 = __half22float2(*(__half2*)&r2.y);
                    float2 d0 = __half22float2(*(__half2*)&r3.x);
                    float2 d1 = __half22float2(*(__half2*)&r3.y);
                    acc[j].x = fmaf(Wt.x, a0.x, fmaf(Wt.y, b0.x,
                               fmaf(Wt.z, c2.x, fmaf(Wt.w, d0.x, acc[j].x))));
                    acc[j].y = fmaf(Wt.x, a0.y, fmaf(Wt.y, b0.y,
                               fmaf(Wt.z, c2.y, fmaf(Wt.w, d0.y, acc[j].y))));
                    acc[j].z = fmaf(Wt.x, a1.x, fmaf(Wt.y, b1.x,
                               fmaf(Wt.z, c3.x, fmaf(Wt.w, d1.x, acc[j].z))));
                    acc[j].w = fmaf(Wt.x, a1.y, fmaf(Wt.y, b1.y,
                               fmaf(Wt.z, c3.y, fmaf(Wt.w, d1.y, acc[j].w))));
                }
            }
        }
        #pragma unroll
        for (int j = 0; j < 4; ++j) {
            int qi = wid + j * 8;
            S[(c0 + 0) * 33 + qi] = acc[j].x;
            S[(c0 + 1) * 33 + qi] = acc[j].y;
            S[(c0 + 2) * 33 + qi] = acc[j].z;
            S[(c0 + 3) * 33 + qi] = acc[j].w;
        }
    }
    __syncthreads();

    for (int e = t; e < EMBED * 32; e += 256) {
        int cc = e >> 5, qi = e & 31;
        int q = q0 + qi;
        if (q < GQ) {
            int oi = (cc * NP + p) * GQ + q;
            out[oi] += S[cc * 33 + qi];
        }
    }
}

// ---------------------------------------------------------------------------
extern "C" void kernel_launch(void* const* d_in, const int* in_sizes, int n_in,
                              void* d_out, int out_size)
{
    const float* f0  = (const float*)d_in[0];
    const float* f1  = (const float*)d_in[1];
    const float* f2  = (const float*)d_in[2];
    const float* f3  = (const float*)d_in[3];
    const float* ref = (const float*)d_in[4];
    const float* l2i = (const float*)d_in[5];
    const float* w1  = (const float*)d_in[6];
    const float* b1  = (const float*)d_in[7];
    const float* w2  = (const float*)d_in[8];
    const float* b2  = (const float*)d_in[9];
    float* out = (float*)d_out;

    k_transpose<<<2960, dim3(32, 8)>>>(f0, f1, f2, f3, w2);

    cudaFuncSetAttribute(k_mlp_mma, cudaFuncAttributeMaxDynamicSharedMemorySize,
                         K1_SMEM);
    k_mlp_mma<<<K1_GRID, 256, K1_SMEM>>>(ref, w1, b1, b2, out);

    dim3 grid((GQ + 31) / 32, NP);
    k_sample<<<grid, 256>>>(ref, l2i, out);
}